// round 3
// baseline (speedup 1.0000x reference)
#include <cuda_runtime.h>
#include <cuda_bf16.h>
#include <cstdint>

#define B_      16
#define LX_     2048
#define H_      1024
#define LOUT_   3072
#define TILE_T  16
#define NTILE   192                 // LOUT_/TILE_T
#define NTILES_TOT (B_*NTILE)       // 3072
#define WIN     60                  // z rows per tile window
#define WTAB    61                  // + 1 prefix row
#define BAND    36
#define AOFF    27
#define TILE_H  512
#define SEG     256
#define NSEG    8                   // LX_/SEG
#define SMEM_BYTES ((WTAB*TILE_H + WTAB*32)*4)   // 132736

typedef unsigned long long ull;

// ---------------- device scratch (no allocs allowed) ----------------
__device__ float  g_P[(size_t)B_*LX_*H_];          // exclusive prefix per segment
__device__ float  g_S[B_*NSEG*H_];                 // segment sums
__device__ float  g_n[B_];                         // valid source lengths
__device__ float2 g_wt[(size_t)NTILES_TOT*WTAB*TILE_T]; // duplicated-pair weights
__device__ int    g_A[NTILES_TOT];                 // window base row per tile
__device__ float  g_Prow[(size_t)NTILES_TOT*H_];   // gathered global prefix row P[A]

// ls may arrive as int64 (as written) or int32 (jax x64 off). Detect at runtime:
// int32 pair packed into first int64 word gives a huge value.
__device__ __forceinline__ int read_ls(const void* p, int b) {
    long long v0 = ((const long long*)p)[0];
    if (v0 > 0 && v0 <= 1000000) return (int)((const long long*)p)[b];
    return ((const int*)p)[b];
}

// ---------------- kn: n[b] = sum(z_mask[b,:]) ----------------
__global__ void kn_kernel(const float* __restrict__ zm) {
    __shared__ float red[256];
    int b = blockIdx.x;
    float s = 0.f;
    for (int i = threadIdx.x; i < LX_; i += 256) s += zm[b*LX_ + i];
    red[threadIdx.x] = s; __syncthreads();
    for (int o = 128; o > 0; o >>= 1) {
        if (threadIdx.x < o) red[threadIdx.x] += red[threadIdx.x + o];
        __syncthreads();
    }
    if (threadIdx.x == 0) g_n[b] = red[0];
}

// ---------------- k1: segmented exclusive prefix sums of z ----------------
// grid (4 hchunks, NSEG, B_), 256 threads; thread owns one h column in its segment.
__global__ void k1_kernel(const float* __restrict__ z) {
    int b = blockIdx.z, seg = blockIdx.y, hc = blockIdx.x;
    int h = hc*256 + threadIdx.x;
    size_t base = ((size_t)(b*LX_ + seg*SEG))*H_ + h;
    const float* src = z + base;
    float* dst = g_P + base;
    float run = 0.f;
    for (int s0 = 0; s0 < SEG; s0 += 8) {
        float v[8];
        #pragma unroll
        for (int k = 0; k < 8; k++) v[k] = src[(size_t)(s0+k)*H_];
        #pragma unroll
        for (int k = 0; k < 8; k++) { dst[(size_t)(s0+k)*H_] = run; run += v[k]; }
    }
    g_S[(size_t)(b*NSEG + seg)*H_ + h] = run;
}

// ---------------- kw: per-tile weight tables ----------------
// One block (64 thr) per (b, t-tile of 16). Table wt[u][t], u=0 is the P-row coeff.
__global__ void kw_kernel(const void* __restrict__ lsp, const float* __restrict__ sigma) {
    int tile = blockIdx.x;
    int b = tile / NTILE;
    int t0 = (tile % NTILE) * TILE_T;
    __shared__ float smu[TILE_T], sps[TILE_T];
    __shared__ int sa[TILE_T], sA;
    float nf = g_n[b];
    int n = (int)(nf + 0.5f);
    int lsb = read_ls(lsp, b);
    float sg = sigma[0];
    float c = 0.5f / (sg*sg);
    int tid = threadIdx.x;
    if (tid < TILE_T) {
        int t = t0 + tid;
        float mu = (float)t * nf / (float)lsb;       // bit-exact vs reference
        int a = (int)ceilf(mu) - AOFF;
        a = a < 0 ? 0 : (a > n ? n : a);
        float sum = (float)a;                        // bridge rows have weight 1
        #pragma unroll
        for (int j = 0; j < BAND; j++) {
            int s = a + j;
            if (s < n) sum += __expf(-c * exp2f((float)s - mu));
        }
        sps[tid] = (t < lsb) ? (1.0f / sum) : 0.0f;
        smu[tid] = mu; sa[tid] = a;
    }
    __syncthreads();
    if (tid == 0) {
        int A = sa[0];
        if (A > n - WIN) A = n - WIN;   // keep window rows < n (in-bounds, zero tail)
        if (A < 0) A = 0;
        sA = A; g_A[tile] = A;
    }
    __syncthreads();
    int A = sA;
    float2* wt = g_wt + (size_t)tile*WTAB*TILE_T;
    for (int idx = tid; idx < WTAB*TILE_T; idx += blockDim.x) {
        int u = idx >> 4, t = idx & 15;
        float w;
        if (u == 0) w = sps[t];                      // coefficient for P[A]
        else {
            int s = A + u - 1;
            if (s < sa[t]) w = sps[t];               // bridge row: weight 1 * inv_denom
            else if (s < sa[t] + BAND && s < n)
                w = sps[t] * __expf(-c * exp2f((float)s - smu[t]));
            else w = 0.0f;
        }
        wt[idx] = make_float2(w, w);                 // duplicated for f32x2 FMA
    }
}

// ---------------- kP: gather global prefix row P[A] per tile ----------------
__global__ void kP_kernel() {
    int tile = blockIdx.x;
    int b = tile / NTILE;
    int A = g_A[tile];
    int seg = A >> 8;
    int h = threadIdx.x * 4;
    float4 v = *(const float4*)(g_P + ((size_t)(b*LX_ + A))*H_ + h);
    for (int j = 0; j < seg; j++) {
        float4 s = *(const float4*)(g_S + (size_t)(b*NSEG + j)*H_ + h);
        v.x += s.x; v.y += s.y; v.z += s.z; v.w += s.w;
    }
    *(float4*)(g_Prow + (size_t)tile*H_ + h) = v;
}

// ---------------- kmask ----------------
__global__ void kmask_kernel(const void* __restrict__ lsp, float* __restrict__ outm) {
    int i = blockIdx.x*256 + threadIdx.x;
    if (i < B_*LOUT_) {
        int b = i / LOUT_, t = i % LOUT_;
        outm[i] = (t < read_ls(lsp, b)) ? 1.0f : 0.0f;
    }
}

// ---------------- k2: banded weighted sum ----------------
__device__ __forceinline__ void fma2(ull &acc, ull a, ull b) {
    asm volatile("fma.rn.f32x2 %0, %1, %2, %0;" : "+l"(acc) : "l"(a), "l"(b));
}
__device__ __forceinline__ void cpasync16(void* dst, const void* src) {
    unsigned s = (unsigned)__cvta_generic_to_shared(dst);
    asm volatile("cp.async.cg.shared.global [%0], [%1], 16;" :: "r"(s), "l"(src));
}

__global__ __launch_bounds__(256, 1) void k2_kernel(const float* __restrict__ z,
                                                    float* __restrict__ out) {
    extern __shared__ float sm[];
    float* zs = sm;                       // WTAB rows x TILE_H floats (row 0 = P row)
    float* ws = sm + WTAB*TILE_H;         // WTAB rows x 32 floats (16 duplicated pairs)
    const int hb = blockIdx.x * TILE_H;
    const int tileInB = blockIdx.y;
    const int b = blockIdx.z;
    const int tile = b*NTILE + tileInB;
    const int tid = threadIdx.x;
    const int A = g_A[tile];
    const float* zbase = z + (size_t)b*LX_*H_ + hb;

    // weight table -> smem
    {
        const float* wsrc = (const float*)(g_wt + (size_t)tile*WTAB*TILE_T);
        for (int i = tid; i < WTAB*32; i += 256) ws[i] = wsrc[i];
    }
    // P row -> zs row 0
    {
        float2 v = *(const float2*)(g_Prow + (size_t)tile*H_ + hb + tid*2);
        *(float2*)(zs + tid*2) = v;
    }

#define ISSUE(c) do { int br_ = (c)*4;                                              \
    { int u_ = tid;       int r_ = u_>>7; int col_ = (u_&127)*4;                    \
      cpasync16(zs + (size_t)(1+br_+r_)*TILE_H + col_,                              \
                zbase + (size_t)(A+br_+r_)*H_ + col_); }                            \
    { int u_ = tid + 256; int r_ = u_>>7; int col_ = (u_&127)*4;                    \
      cpasync16(zs + (size_t)(1+br_+r_)*TILE_H + col_,                              \
                zbase + (size_t)(A+br_+r_)*H_ + col_); } } while (0)

    ISSUE(0); asm volatile("cp.async.commit_group;");
    ISSUE(1); asm volatile("cp.async.commit_group;");
    ISSUE(2); asm volatile("cp.async.commit_group;");
    __syncthreads();   // P row + weight table visible

    const int tsub = tid >> 7;    // 0..1 : which 8-t subtile
    const int hq   = tid & 127;   // 0..127: which 4-h group
    ull acc[8][2];
    #pragma unroll
    for (int i = 0; i < 8; i++) { acc[i][0] = 0ull; acc[i][1] = 0ull; }

    // u = 0: prefix row (coefficient = pscale[t])
    {
        const ull* zp = (const ull*)zs + hq*2;
        ull z01 = zp[0], z23 = zp[1];
        const ull* wp = (const ull*)ws + tsub*8;
        #pragma unroll
        for (int i = 0; i < 8; i++) { ull w = wp[i]; fma2(acc[i][0], z01, w); fma2(acc[i][1], z23, w); }
    }

    const int NCHUNK = WIN/4;   // 15
    for (int c = 0; c < NCHUNK; c++) {
        asm volatile("cp.async.wait_group 2;");
        __syncthreads();
        if (c + 3 < NCHUNK) { ISSUE(c+3); }
        asm volatile("cp.async.commit_group;");   // keep group count uniform
        #pragma unroll
        for (int r = 0; r < 4; r++) {
            int u = 1 + c*4 + r;
            const ull* zp = (const ull*)(zs + (size_t)u*TILE_H) + hq*2;
            ull z01 = zp[0], z23 = zp[1];
            const ull* wp = (const ull*)(ws + (size_t)u*32) + tsub*8;
            #pragma unroll
            for (int i = 0; i < 8; i++) { ull w = wp[i]; fma2(acc[i][0], z01, w); fma2(acc[i][1], z23, w); }
        }
    }
#undef ISSUE

    // epilogue: unpack + store 8t x 4h per thread
    const int tg = tileInB*TILE_T + tsub*8;
    float* ob = out + ((size_t)b*LOUT_ + tg)*H_ + hb + hq*4;
    #pragma unroll
    for (int i = 0; i < 8; i++) {
        float4 r;
        asm volatile("mov.b64 {%0,%1}, %2;" : "=f"(r.x), "=f"(r.y) : "l"(acc[i][0]));
        asm volatile("mov.b64 {%0,%1}, %2;" : "=f"(r.z), "=f"(r.w) : "l"(acc[i][1]));
        *(float4*)(ob + (size_t)i*H_) = r;
    }
}

// ---------------- launch ----------------
extern "C" void kernel_launch(void* const* d_in, const int* in_sizes, int n_in,
                              void* d_out, int out_size) {
    const float* z     = (const float*)d_in[0];
    const void*  ls    = d_in[1];
    const float* zmask = (const float*)d_in[2];
    const float* sigma = (const float*)d_in[3];
    float* out  = (float*)d_out;
    float* outm = out + (size_t)B_*LOUT_*H_;

    cudaFuncSetAttribute(k2_kernel, cudaFuncAttributeMaxDynamicSharedMemorySize, SMEM_BYTES);

    kn_kernel<<<B_, 256>>>(zmask);
    k1_kernel<<<dim3(4, NSEG, B_), 256>>>(z);
    kw_kernel<<<NTILES_TOT, 64>>>(ls, sigma);
    kP_kernel<<<NTILES_TOT, 256>>>();
    kmask_kernel<<<(B_*LOUT_ + 255)/256, 256>>>(ls, outm);
    k2_kernel<<<dim3(2, NTILE, B_), 256, SMEM_BYTES>>>(z, out);
}

// round 4
// speedup vs baseline: 1.2820x; 1.2820x over previous
#include <cuda_runtime.h>
#include <cuda_bf16.h>
#include <cstdint>

#define B_      16
#define LX_     2048
#define H_      1024
#define LOUT_   3072
#define TILE_T  16
#define NTILE   192                 // LOUT_/TILE_T
#define NTILES_TOT (B_*NTILE)       // 3072
#define WIN     44                  // z rows per tile window (>= 22 slide + 23 band, mult of 4)
#define WTAB    45                  // + 1 prefix row
#define BAND    23                  // d in [-17, 6)
#define AOFF    17
#define TILE_H  512
#define SEG     256
#define NSEG    8                   // LX_/SEG
#define SMEM_BYTES ((WTAB*TILE_H + WTAB*32)*4)   // 97920

typedef unsigned long long ull;

// ---------------- device scratch (no allocs allowed) ----------------
__device__ float  g_P[(size_t)B_*LX_*H_];          // exclusive prefix per segment
__device__ float  g_S[B_*NSEG*H_];                 // segment sums
__device__ float  g_n[B_];                         // valid source lengths
__device__ float2 g_wt[(size_t)NTILES_TOT*WTAB*TILE_T]; // duplicated-pair weights
__device__ int    g_A[NTILES_TOT];                 // window base row per tile
__device__ float  g_Prow[(size_t)NTILES_TOT*H_];   // gathered global prefix row P[A]

// ls may arrive as int64 or int32; detect at runtime.
__device__ __forceinline__ int read_ls(const void* p, int b) {
    long long v0 = ((const long long*)p)[0];
    if (v0 > 0 && v0 <= 1000000) return (int)((const long long*)p)[b];
    return ((const int*)p)[b];
}

// ---------------- kn: n[b] = sum(z_mask[b,:]) ----------------
__global__ void kn_kernel(const float* __restrict__ zm) {
    __shared__ float red[256];
    int b = blockIdx.x;
    float s = 0.f;
    for (int i = threadIdx.x; i < LX_; i += 256) s += zm[b*LX_ + i];
    red[threadIdx.x] = s; __syncthreads();
    for (int o = 128; o > 0; o >>= 1) {
        if (threadIdx.x < o) red[threadIdx.x] += red[threadIdx.x + o];
        __syncthreads();
    }
    if (threadIdx.x == 0) g_n[b] = red[0];
}

// ---------------- k1: segmented exclusive prefix sums of z ----------------
__global__ void k1_kernel(const float* __restrict__ z) {
    int b = blockIdx.z, seg = blockIdx.y, hc = blockIdx.x;
    int h = hc*256 + threadIdx.x;
    size_t base = ((size_t)(b*LX_ + seg*SEG))*H_ + h;
    const float* src = z + base;
    float* dst = g_P + base;
    float run = 0.f;
    for (int s0 = 0; s0 < SEG; s0 += 8) {
        float v[8];
        #pragma unroll
        for (int k = 0; k < 8; k++) v[k] = src[(size_t)(s0+k)*H_];
        #pragma unroll
        for (int k = 0; k < 8; k++) { dst[(size_t)(s0+k)*H_] = run; run += v[k]; }
    }
    g_S[(size_t)(b*NSEG + seg)*H_ + h] = run;
}

// ---------------- kw: per-tile weight tables ----------------
__global__ void kw_kernel(const void* __restrict__ lsp, const float* __restrict__ sigma) {
    int tile = blockIdx.x;
    int b = tile / NTILE;
    int t0 = (tile % NTILE) * TILE_T;
    __shared__ float smu[TILE_T], sps[TILE_T];
    __shared__ int sa[TILE_T], sA;
    float nf = g_n[b];
    int n = (int)(nf + 0.5f);
    int lsb = read_ls(lsp, b);
    float sg = sigma[0];
    float c = 0.5f / (sg*sg);
    int tid = threadIdx.x;
    if (tid < TILE_T) {
        int t = t0 + tid;
        float mu = (float)t * nf / (float)lsb;       // bit-exact vs reference
        int a = (int)ceilf(mu) - AOFF;
        a = a < 0 ? 0 : (a > n ? n : a);
        float sum = (float)a;                        // rows below band have weight ~1
        #pragma unroll
        for (int j = 0; j < BAND; j++) {
            int s = a + j;
            if (s < n) sum += __expf(-c * exp2f((float)s - mu));
        }
        sps[tid] = (t < lsb) ? (1.0f / sum) : 0.0f;
        smu[tid] = mu; sa[tid] = a;
    }
    __syncthreads();
    if (tid == 0) {
        int A = sa[0];
        if (A > n - WIN) A = n - WIN;   // keep window rows < n (in-bounds, zero tail)
        if (A < 0) A = 0;
        sA = A; g_A[tile] = A;
    }
    __syncthreads();
    int A = sA;
    float2* wt = g_wt + (size_t)tile*WTAB*TILE_T;
    for (int idx = tid; idx < WTAB*TILE_T; idx += blockDim.x) {
        int u = idx >> 4, t = idx & 15;
        float w;
        if (u == 0) w = sps[t];                      // coefficient for P[A]
        else {
            int s = A + u - 1;
            if (s < sa[t]) w = sps[t];               // bridge row: weight 1 * inv_denom
            else if (s < sa[t] + BAND && s < n)
                w = sps[t] * __expf(-c * exp2f((float)s - smu[t]));
            else w = 0.0f;
        }
        wt[idx] = make_float2(w, w);                 // duplicated for f32x2 FMA
    }
}

// ---------------- kP: gather global prefix row P[A] per tile ----------------
__global__ void kP_kernel() {
    int tile = blockIdx.x;
    int b = tile / NTILE;
    int A = g_A[tile];
    int seg = A >> 8;
    int h = threadIdx.x * 4;
    float4 v = *(const float4*)(g_P + ((size_t)(b*LX_ + A))*H_ + h);
    for (int j = 0; j < seg; j++) {
        float4 s = *(const float4*)(g_S + (size_t)(b*NSEG + j)*H_ + h);
        v.x += s.x; v.y += s.y; v.z += s.z; v.w += s.w;
    }
    *(float4*)(g_Prow + (size_t)tile*H_ + h) = v;
}

// ---------------- kmask ----------------
__global__ void kmask_kernel(const void* __restrict__ lsp, float* __restrict__ outm) {
    int i = blockIdx.x*256 + threadIdx.x;
    if (i < B_*LOUT_) {
        int b = i / LOUT_, t = i % LOUT_;
        outm[i] = (t < read_ls(lsp, b)) ? 1.0f : 0.0f;
    }
}

// ---------------- k2: banded weighted sum ----------------
__device__ __forceinline__ void fma2(ull &acc, ull a, ull b) {
    asm volatile("fma.rn.f32x2 %0, %1, %2, %0;" : "+l"(acc) : "l"(a), "l"(b));
}
__device__ __forceinline__ void cpasync16(void* dst, const void* src) {
    unsigned s = (unsigned)__cvta_generic_to_shared(dst);
    asm volatile("cp.async.cg.shared.global [%0], [%1], 16;" :: "r"(s), "l"(src));
}

__global__ __launch_bounds__(256, 2) void k2_kernel(const float* __restrict__ z,
                                                    float* __restrict__ out) {
    extern __shared__ float sm[];
    float* zs = sm;                       // WTAB rows x TILE_H floats (row 0 = P row)
    float* ws = sm + WTAB*TILE_H;         // WTAB rows x 32 floats (16 duplicated pairs)
    const int hb = blockIdx.x * TILE_H;
    const int tileInB = blockIdx.y;
    const int b = blockIdx.z;
    const int tile = b*NTILE + tileInB;
    const int tid = threadIdx.x;
    const int A = g_A[tile];
    const float* zbase = z + (size_t)b*LX_*H_ + hb;

    // weight table -> smem
    {
        const float* wsrc = (const float*)(g_wt + (size_t)tile*WTAB*TILE_T);
        for (int i = tid; i < WTAB*32; i += 256) ws[i] = wsrc[i];
    }
    // P row -> zs row 0
    {
        float2 v = *(const float2*)(g_Prow + (size_t)tile*H_ + hb + tid*2);
        *(float2*)(zs + tid*2) = v;
    }

#define ISSUE(c) do { int br_ = (c)*4;                                              \
    { int u_ = tid;       int r_ = u_>>7; int col_ = (u_&127)*4;                    \
      cpasync16(zs + (size_t)(1+br_+r_)*TILE_H + col_,                              \
                zbase + (size_t)(A+br_+r_)*H_ + col_); }                            \
    { int u_ = tid + 256; int r_ = u_>>7; int col_ = (u_&127)*4;                    \
      cpasync16(zs + (size_t)(1+br_+r_)*TILE_H + col_,                              \
                zbase + (size_t)(A+br_+r_)*H_ + col_); } } while (0)

    ISSUE(0); asm volatile("cp.async.commit_group;");
    ISSUE(1); asm volatile("cp.async.commit_group;");
    ISSUE(2); asm volatile("cp.async.commit_group;");
    ISSUE(3); asm volatile("cp.async.commit_group;");
    __syncthreads();   // P row + weight table visible

    const int tsub = tid >> 7;    // 0..1 : which 8-t subtile
    const int hq   = tid & 127;   // 0..127: which 4-h group
    ull acc[8][2];
    #pragma unroll
    for (int i = 0; i < 8; i++) { acc[i][0] = 0ull; acc[i][1] = 0ull; }

    // u = 0: prefix row (coefficient = pscale[t])
    {
        ulonglong2 zz = *((const ulonglong2*)zs + hq);
        const ulonglong2* wp = (const ulonglong2*)ws + tsub*4;
        #pragma unroll
        for (int j = 0; j < 4; j++) {
            ulonglong2 w2 = wp[j];
            fma2(acc[2*j][0],   zz.x, w2.x); fma2(acc[2*j][1],   zz.y, w2.x);
            fma2(acc[2*j+1][0], zz.x, w2.y); fma2(acc[2*j+1][1], zz.y, w2.y);
        }
    }

    const int NCHUNK = WIN/4;   // 11
    for (int c = 0; c < NCHUNK; c++) {
        asm volatile("cp.async.wait_group 3;");
        __syncthreads();
        if (c + 4 < NCHUNK) { ISSUE(c+4); }
        asm volatile("cp.async.commit_group;");   // keep group count uniform
        #pragma unroll
        for (int r = 0; r < 4; r++) {
            int u = 1 + c*4 + r;
            ulonglong2 zz = *((const ulonglong2*)(zs + (size_t)u*TILE_H) + hq);
            const ulonglong2* wp = (const ulonglong2*)(ws + (size_t)u*32) + tsub*4;
            #pragma unroll
            for (int j = 0; j < 4; j++) {
                ulonglong2 w2 = wp[j];
                fma2(acc[2*j][0],   zz.x, w2.x); fma2(acc[2*j][1],   zz.y, w2.x);
                fma2(acc[2*j+1][0], zz.x, w2.y); fma2(acc[2*j+1][1], zz.y, w2.y);
            }
        }
    }
#undef ISSUE

    // epilogue: unpack + store 8t x 4h per thread
    const int tg = tileInB*TILE_T + tsub*8;
    float* ob = out + ((size_t)b*LOUT_ + tg)*H_ + hb + hq*4;
    #pragma unroll
    for (int i = 0; i < 8; i++) {
        float4 r;
        asm volatile("mov.b64 {%0,%1}, %2;" : "=f"(r.x), "=f"(r.y) : "l"(acc[i][0]));
        asm volatile("mov.b64 {%0,%1}, %2;" : "=f"(r.z), "=f"(r.w) : "l"(acc[i][1]));
        *(float4*)(ob + (size_t)i*H_) = r;
    }
}

// ---------------- launch ----------------
extern "C" void kernel_launch(void* const* d_in, const int* in_sizes, int n_in,
                              void* d_out, int out_size) {
    const float* z     = (const float*)d_in[0];
    const void*  ls    = d_in[1];
    const float* zmask = (const float*)d_in[2];
    const float* sigma = (const float*)d_in[3];
    float* out  = (float*)d_out;
    float* outm = out + (size_t)B_*LOUT_*H_;

    cudaFuncSetAttribute(k2_kernel, cudaFuncAttributeMaxDynamicSharedMemorySize, SMEM_BYTES);

    kn_kernel<<<B_, 256>>>(zmask);
    k1_kernel<<<dim3(4, NSEG, B_), 256>>>(z);
    kw_kernel<<<NTILES_TOT, 64>>>(ls, sigma);
    kP_kernel<<<NTILES_TOT, 256>>>();
    kmask_kernel<<<(B_*LOUT_ + 255)/256, 256>>>(ls, outm);
    k2_kernel<<<dim3(2, NTILE, B_), 256, SMEM_BYTES>>>(z, out);
}

// round 7
// speedup vs baseline: 2.4774x; 1.9324x over previous
#include <cuda_runtime.h>
#include <cuda_bf16.h>
#include <cstdint>

#define B_      16
#define LX_     2048
#define H_      1024
#define LOUT_   3072
#define TILE_T  16
#define NTILE   192                 // LOUT_/TILE_T
#define NTILES_TOT (B_*NTILE)       // 3072
#define WIN     44                  // z rows per tile window
#define WTAB    45                  // + 1 prefix row
#define BAND    23                  // d in [-17, 6)
#define AOFF    17
#define TILE_H  512
#define SEG     256
#define NSEG    8                   // LX_/SEG

typedef unsigned long long ull;

// ---------------- device scratch (no allocs allowed) ----------------
__device__ float  g_P[(size_t)B_*LX_*H_];          // exclusive prefix per segment
__device__ float  g_S[B_*NSEG*H_];                 // segment sums
__device__ float  g_n[B_];                         // valid source lengths
__device__ float2 g_wt[(size_t)NTILES_TOT*WTAB*TILE_T]; // duplicated-pair weights
__device__ int    g_A[NTILES_TOT];                 // window base row per tile
__device__ float  g_Prow[(size_t)NTILES_TOT*H_];   // gathered global prefix row P[A]

// ls may arrive as int64 or int32; detect at runtime.
__device__ __forceinline__ int read_ls(const void* p, int b) {
    long long v0 = ((const long long*)p)[0];
    if (v0 > 0 && v0 <= 1000000) return (int)((const long long*)p)[b];
    return ((const int*)p)[b];
}

// ---------------- kn: n[b] = sum(z_mask[b,:]) ----------------
__global__ void kn_kernel(const float* __restrict__ zm) {
    __shared__ float red[256];
    int b = blockIdx.x;
    float s = 0.f;
    for (int i = threadIdx.x; i < LX_; i += 256) s += zm[b*LX_ + i];
    red[threadIdx.x] = s; __syncthreads();
    for (int o = 128; o > 0; o >>= 1) {
        if (threadIdx.x < o) red[threadIdx.x] += red[threadIdx.x + o];
        __syncthreads();
    }
    if (threadIdx.x == 0) g_n[b] = red[0];
}

// ---------------- k1: segmented exclusive prefix sums of z ----------------
__global__ void k1_kernel(const float* __restrict__ z) {
    int b = blockIdx.z, seg = blockIdx.y, hc = blockIdx.x;
    int h = hc*256 + threadIdx.x;
    size_t base = ((size_t)(b*LX_ + seg*SEG))*H_ + h;
    const float* src = z + base;
    float* dst = g_P + base;
    float run = 0.f;
    for (int s0 = 0; s0 < SEG; s0 += 8) {
        float v[8];
        #pragma unroll
        for (int k = 0; k < 8; k++) v[k] = src[(size_t)(s0+k)*H_];
        #pragma unroll
        for (int k = 0; k < 8; k++) { dst[(size_t)(s0+k)*H_] = run; run += v[k]; }
    }
    g_S[(size_t)(b*NSEG + seg)*H_ + h] = run;
}

// ---------------- kw: per-tile weight tables ----------------
__global__ void kw_kernel(const void* __restrict__ lsp, const float* __restrict__ sigma) {
    int tile = blockIdx.x;
    int b = tile / NTILE;
    int t0 = (tile % NTILE) * TILE_T;
    __shared__ float smu[TILE_T], sps[TILE_T];
    __shared__ int sa[TILE_T], sA;
    float nf = g_n[b];
    int n = (int)(nf + 0.5f);
    int lsb = read_ls(lsp, b);
    float sg = sigma[0];
    float c = 0.5f / (sg*sg);
    int tid = threadIdx.x;
    if (tid < TILE_T) {
        int t = t0 + tid;
        float mu = (float)t * nf / (float)lsb;       // bit-exact vs reference
        int a = (int)ceilf(mu) - AOFF;
        a = a < 0 ? 0 : (a > n ? n : a);
        float sum = (float)a;                        // rows below band have weight ~1
        #pragma unroll
        for (int j = 0; j < BAND; j++) {
            int s = a + j;
            if (s < n) sum += __expf(-c * exp2f((float)s - mu));
        }
        sps[tid] = (t < lsb) ? (1.0f / sum) : 0.0f;
        smu[tid] = mu; sa[tid] = a;
    }
    __syncthreads();
    if (tid == 0) {
        int A = sa[0];
        if (A > n - WIN) A = n - WIN;   // keep window rows < n (in-bounds, zero tail)
        if (A < 0) A = 0;
        sA = A; g_A[tile] = A;
    }
    __syncthreads();
    int A = sA;
    float2* wt = g_wt + (size_t)tile*WTAB*TILE_T;
    for (int idx = tid; idx < WTAB*TILE_T; idx += blockDim.x) {
        int u = idx >> 4, t = idx & 15;
        float w;
        if (u == 0) w = sps[t];                      // coefficient for P[A]
        else {
            int s = A + u - 1;
            if (s < sa[t]) w = sps[t];               // bridge row: weight 1 * inv_denom
            else if (s < sa[t] + BAND && s < n)
                w = sps[t] * __expf(-c * exp2f((float)s - smu[t]));
            else w = 0.0f;
        }
        wt[idx] = make_float2(w, w);                 // duplicated for f32x2 FMA
    }
}

// ---------------- kP: gather global prefix row P[A] per tile ----------------
__global__ void kP_kernel() {
    int tile = blockIdx.x;
    int b = tile / NTILE;
    int A = g_A[tile];
    int seg = A >> 8;
    int h = threadIdx.x * 4;
    float4 v = *(const float4*)(g_P + ((size_t)(b*LX_ + A))*H_ + h);
    for (int j = 0; j < seg; j++) {
        float4 s = *(const float4*)(g_S + (size_t)(b*NSEG + j)*H_ + h);
        v.x += s.x; v.y += s.y; v.z += s.z; v.w += s.w;
    }
    *(float4*)(g_Prow + (size_t)tile*H_ + h) = v;
}

// ---------------- kmask ----------------
__global__ void kmask_kernel(const void* __restrict__ lsp, float* __restrict__ outm) {
    int i = blockIdx.x*256 + threadIdx.x;
    if (i < B_*LOUT_) {
        int b = i / LOUT_, t = i % LOUT_;
        outm[i] = (t < read_ls(lsp, b)) ? 1.0f : 0.0f;
    }
}

// ---------------- k2: banded weighted sum (register-pipelined LDG, no z smem) ----
__device__ __forceinline__ void fma2(ull &acc, ull a, ull b) {
    asm volatile("fma.rn.f32x2 %0, %1, %2, %0;" : "+l"(acc) : "l"(a), "l"(b));
}

#define PFD 4   // register prefetch depth

__global__ __launch_bounds__(256, 3) void k2_kernel(const float* __restrict__ z,
                                                    float* __restrict__ out) {
    __shared__ float ws[WTAB*32];         // 45 rows x 16 duplicated weight pairs
    const int hb = blockIdx.x * TILE_H;
    const int tileInB = blockIdx.y;
    const int b = blockIdx.z;
    const int tile = b*NTILE + tileInB;
    const int tid = threadIdx.x;
    const int A = g_A[tile];
    const int tsub = tid >> 7;    // 0..1 : which 8-t subtile
    const int hq   = tid & 127;   // 0..127: which 4-h group

    // weight table -> smem (one-time)
    {
        const float4* wsrc = (const float4*)(g_wt + (size_t)tile*WTAB*TILE_T);
        #pragma unroll
        for (int i = tid; i < WTAB*32/4; i += 256) ((float4*)ws)[i] = wsrc[i];
    }

    const float* zcol = z + (size_t)b*LX_*H_ + hb + hq*4;

    ull acc[8][2];
    #pragma unroll
    for (int i = 0; i < 8; i++) { acc[i][0] = 0ull; acc[i][1] = 0ull; }

    // register prefetch pipeline for z rows A..A+WIN-1
    ulonglong2 zr[PFD];
    #pragma unroll
    for (int d = 0; d < PFD; d++) {
        int r = A + d; if (r > LX_-1) r = LX_-1;
        zr[d] = *(const ulonglong2*)(zcol + (size_t)r*H_);
    }
    // P row (u = 0) straight from global
    ulonglong2 pz = *(const ulonglong2*)(g_Prow + (size_t)tile*H_ + hb + hq*4);

    __syncthreads();   // ws visible

    // u = 0: prefix row
    {
        const ulonglong2* wp = (const ulonglong2*)ws + tsub*4;
        #pragma unroll
        for (int j = 0; j < 4; j++) {
            ulonglong2 w2 = wp[j];
            fma2(acc[2*j][0],   pz.x, w2.x); fma2(acc[2*j][1],   pz.y, w2.x);
            fma2(acc[2*j+1][0], pz.x, w2.y); fma2(acc[2*j+1][1], pz.y, w2.y);
        }
    }

    #pragma unroll
    for (int u = 0; u < WIN; u++) {
        ulonglong2 cur = zr[u & (PFD-1)];
        int pf = A + u + PFD; if (pf > LX_-1) pf = LX_-1;   // tail prefetch never consumed
        zr[u & (PFD-1)] = *(const ulonglong2*)(zcol + (size_t)pf*H_);
        const ulonglong2* wp = (const ulonglong2*)(ws + (size_t)(u+1)*32) + tsub*4;
        #pragma unroll
        for (int j = 0; j < 4; j++) {
            ulonglong2 w2 = wp[j];
            fma2(acc[2*j][0],   cur.x, w2.x); fma2(acc[2*j][1],   cur.y, w2.x);
            fma2(acc[2*j+1][0], cur.x, w2.y); fma2(acc[2*j+1][1], cur.y, w2.y);
        }
    }

    // epilogue: unpack + store 8t x 4h per thread
    const int tg = tileInB*TILE_T + tsub*8;
    float* ob = out + ((size_t)b*LOUT_ + tg)*H_ + hb + hq*4;
    #pragma unroll
    for (int i = 0; i < 8; i++) {
        float4 r;
        asm volatile("mov.b64 {%0,%1}, %2;" : "=f"(r.x), "=f"(r.y) : "l"(acc[i][0]));
        asm volatile("mov.b64 {%0,%1}, %2;" : "=f"(r.z), "=f"(r.w) : "l"(acc[i][1]));
        *(float4*)(ob + (size_t)i*H_) = r;
    }
}

// ---------------- launch ----------------
extern "C" void kernel_launch(void* const* d_in, const int* in_sizes, int n_in,
                              void* d_out, int out_size) {
    const float* z     = (const float*)d_in[0];
    const void*  ls    = d_in[1];
    const float* zmask = (const float*)d_in[2];
    const float* sigma = (const float*)d_in[3];
    float* out  = (float*)d_out;
    float* outm = out + (size_t)B_*LOUT_*H_;

    kn_kernel<<<B_, 256>>>(zmask);
    k1_kernel<<<dim3(4, NSEG, B_), 256>>>(z);
    kw_kernel<<<NTILES_TOT, 64>>>(ls, sigma);
    kP_kernel<<<NTILES_TOT, 256>>>();
    kmask_kernel<<<(B_*LOUT_ + 255)/256, 256>>>(ls, outm);
    k2_kernel<<<dim3(2, NTILE, B_), 256>>>(z, out);
}

// round 8
// speedup vs baseline: 2.7412x; 1.1065x over previous
#include <cuda_runtime.h>
#include <cuda_bf16.h>
#include <cstdint>

#define B_      16
#define LX_     2048
#define H_      1024
#define LOUT_   3072
#define TILE_T  16
#define NTILE   192                 // LOUT_/TILE_T
#define NTILES_TOT (B_*NTILE)       // 3072
#define WIN     36                  // z rows per tile window: slide(20) + BAND(16)
#define WTAB    37                  // + 1 prefix row
#define BAND    16                  // d in (-11, 5)
#define AOFF    11
#define TILE_H  512
#define CCH     8                   // prefix chunk rows
#define NCH     256                 // LX_/CCH

typedef unsigned long long ull;

// ---------------- device scratch (no allocs allowed) ----------------
__device__ float  g_C[(size_t)B_*NCH*H_];          // chunk sums -> exclusive chunk prefix
__device__ float  g_n[B_];                         // valid source lengths
__device__ float2 g_wt[(size_t)NTILES_TOT*WTAB*TILE_T]; // duplicated-pair weights
__device__ int    g_A[NTILES_TOT];                 // window base row per tile

// ls may arrive as int64 or int32; detect at runtime.
__device__ __forceinline__ int read_ls(const void* p, int b) {
    long long v0 = ((const long long*)p)[0];
    if (v0 > 0 && v0 <= 1000000) return (int)((const long long*)p)[b];
    return ((const int*)p)[b];
}

// ---------------- kn: n[b] = sum(z_mask[b,:]) ----------------
__global__ void kn_kernel(const float* __restrict__ zm) {
    __shared__ float red[256];
    int b = blockIdx.x;
    float s = 0.f;
    for (int i = threadIdx.x; i < LX_; i += 256) s += zm[b*LX_ + i];
    red[threadIdx.x] = s; __syncthreads();
    for (int o = 128; o > 0; o >>= 1) {
        if (threadIdx.x < o) red[threadIdx.x] += red[threadIdx.x + o];
        __syncthreads();
    }
    if (threadIdx.x == 0) g_n[b] = red[0];
}

// ---------------- k1c: 8-row chunk sums of z ----------------
__global__ void k1c_kernel(const float* __restrict__ z) {
    int ch = blockIdx.x, b = blockIdx.y;
    int h4 = threadIdx.x * 4;
    const float* src = z + ((size_t)(b*LX_ + ch*CCH))*H_ + h4;
    float4 s = make_float4(0.f, 0.f, 0.f, 0.f);
    #pragma unroll
    for (int k = 0; k < CCH; k++) {
        float4 v = *(const float4*)(src + (size_t)k*H_);
        s.x += v.x; s.y += v.y; s.z += v.z; s.w += v.w;
    }
    *(float4*)(g_C + ((size_t)(b*NCH + ch))*H_ + h4) = s;
}

// ---------------- k1p: in-place exclusive prefix over chunk rows ----------------
__global__ void k1p_kernel() {
    int b = blockIdx.y;
    int h = blockIdx.x*256 + threadIdx.x;
    float* col = g_C + (size_t)b*NCH*H_ + h;
    float run = 0.f;
    for (int c0 = 0; c0 < NCH; c0 += 8) {
        float v[8];
        #pragma unroll
        for (int k = 0; k < 8; k++) v[k] = col[(size_t)(c0+k)*H_];
        #pragma unroll
        for (int k = 0; k < 8; k++) { float t = v[k]; col[(size_t)(c0+k)*H_] = run; run += t; }
    }
}

// ---------------- kw: per-tile weight tables + output mask ----------------
__global__ void kw_kernel(const void* __restrict__ lsp, const float* __restrict__ sigma,
                          float* __restrict__ outm) {
    int tile = blockIdx.x;
    int b = tile / NTILE;
    int t0 = (tile % NTILE) * TILE_T;
    __shared__ float smu[TILE_T], sps[TILE_T];
    __shared__ int sa[TILE_T], sA;
    float nf = g_n[b];
    int n = (int)(nf + 0.5f);
    int lsb = read_ls(lsp, b);
    float sg = sigma[0];
    float c = 0.5f / (sg*sg);
    int tid = threadIdx.x;
    if (tid < TILE_T) {
        int t = t0 + tid;
        float mu = (float)t * nf / (float)lsb;       // bit-exact vs reference
        int a = (int)ceilf(mu) - AOFF;
        a = a < 0 ? 0 : (a > n ? n : a);
        float sum = (float)a;                        // rows below band have weight ~1
        #pragma unroll
        for (int j = 0; j < BAND; j++) {
            int s = a + j;
            if (s < n) sum += __expf(-c * exp2f((float)s - mu));
        }
        float m = (t < lsb) ? 1.0f : 0.0f;
        sps[tid] = m / sum;
        smu[tid] = mu; sa[tid] = a;
        outm[b*LOUT_ + t] = m;                       // output mask (fused)
    }
    __syncthreads();
    if (tid == 0) {
        int A = sa[0];
        if (A > n - WIN) A = n - WIN;   // keep window rows < n (in-bounds, zero tail)
        if (A < 0) A = 0;
        sA = A; g_A[tile] = A;
    }
    __syncthreads();
    int A = sA;
    float2* wt = g_wt + (size_t)tile*WTAB*TILE_T;
    for (int idx = tid; idx < WTAB*TILE_T; idx += blockDim.x) {
        int u = idx >> 4, t = idx & 15;
        float w;
        if (u == 0) w = sps[t];                      // coefficient for P[A]
        else {
            int s = A + u - 1;
            if (s < sa[t]) w = sps[t];               // bridge row: weight 1 * inv_denom
            else if (s < sa[t] + BAND && s < n)
                w = sps[t] * __expf(-c * exp2f((float)s - smu[t]));
            else w = 0.0f;
        }
        wt[idx] = make_float2(w, w);                 // duplicated for f32x2 FMA
    }
}

// ---------------- k2: banded weighted sum (register-pipelined LDG) ----------------
__device__ __forceinline__ void fma2(ull &acc, ull a, ull b) {
    asm volatile("fma.rn.f32x2 %0, %1, %2, %0;" : "+l"(acc) : "l"(a), "l"(b));
}
__device__ __forceinline__ ull packf2(float lo, float hi) {
    ull r;
    asm("mov.b64 %0, {%1,%2};" : "=l"(r) : "f"(lo), "f"(hi));
    return r;
}

#define PFD 4   // register prefetch depth

__global__ __launch_bounds__(256, 3) void k2_kernel(const float* __restrict__ z,
                                                    float* __restrict__ out) {
    __shared__ float ws[WTAB*32];         // 37 rows x 16 duplicated weight pairs
    const int hb = blockIdx.x * TILE_H;
    const int tileInB = blockIdx.y;
    const int b = blockIdx.z;
    const int tile = b*NTILE + tileInB;
    const int tid = threadIdx.x;
    const int A = g_A[tile];
    const int tsub = tid >> 7;    // 0..1 : which 8-t subtile
    const int hq   = tid & 127;   // 0..127: which 4-h group

    // weight table -> smem (one-time)
    {
        const float4* wsrc = (const float4*)(g_wt + (size_t)tile*WTAB*TILE_T);
        #pragma unroll
        for (int i = tid; i < WTAB*32/4; i += 256) ((float4*)ws)[i] = wsrc[i];
    }

    const float* zcol = z + (size_t)b*LX_*H_ + hb + hq*4;

    ull acc[8][2];
    #pragma unroll
    for (int i = 0; i < 8; i++) { acc[i][0] = 0ull; acc[i][1] = 0ull; }

    // register prefetch pipeline for z rows A..A+WIN-1
    ulonglong2 zr[PFD];
    #pragma unroll
    for (int d = 0; d < PFD; d++) {
        int r = A + d; if (r > LX_-1) r = LX_-1;
        zr[d] = *(const ulonglong2*)(zcol + (size_t)r*H_);
    }

    // reconstruct prefix row P[A] = Cpref[A>>3] + residual z rows [8c, A)
    ulonglong2 pz;
    {
        int c8 = A >> 3, r0 = c8 << 3;
        float4 p4 = *(const float4*)(g_C + ((size_t)(b*NCH + c8))*H_ + hb + hq*4);
        for (int r = r0; r < A; r++) {
            float4 v = *(const float4*)(zcol + (size_t)r*H_);
            p4.x += v.x; p4.y += v.y; p4.z += v.z; p4.w += v.w;
        }
        pz.x = packf2(p4.x, p4.y);
        pz.y = packf2(p4.z, p4.w);
    }

    __syncthreads();   // ws visible

    // u = 0: prefix row
    {
        const ulonglong2* wp = (const ulonglong2*)ws + tsub*4;
        #pragma unroll
        for (int j = 0; j < 4; j++) {
            ulonglong2 w2 = wp[j];
            fma2(acc[2*j][0],   pz.x, w2.x); fma2(acc[2*j][1],   pz.y, w2.x);
            fma2(acc[2*j+1][0], pz.x, w2.y); fma2(acc[2*j+1][1], pz.y, w2.y);
        }
    }

    #pragma unroll
    for (int u = 0; u < WIN; u++) {
        ulonglong2 cur = zr[u & (PFD-1)];
        int pf = A + u + PFD; if (pf > LX_-1) pf = LX_-1;   // tail prefetch never consumed
        zr[u & (PFD-1)] = *(const ulonglong2*)(zcol + (size_t)pf*H_);
        const ulonglong2* wp = (const ulonglong2*)(ws + (size_t)(u+1)*32) + tsub*4;
        #pragma unroll
        for (int j = 0; j < 4; j++) {
            ulonglong2 w2 = wp[j];
            fma2(acc[2*j][0],   cur.x, w2.x); fma2(acc[2*j][1],   cur.y, w2.x);
            fma2(acc[2*j+1][0], cur.x, w2.y); fma2(acc[2*j+1][1], cur.y, w2.y);
        }
    }

    // epilogue: unpack + store 8t x 4h per thread
    const int tg = tileInB*TILE_T + tsub*8;
    float* ob = out + ((size_t)b*LOUT_ + tg)*H_ + hb + hq*4;
    #pragma unroll
    for (int i = 0; i < 8; i++) {
        float4 r;
        asm volatile("mov.b64 {%0,%1}, %2;" : "=f"(r.x), "=f"(r.y) : "l"(acc[i][0]));
        asm volatile("mov.b64 {%0,%1}, %2;" : "=f"(r.z), "=f"(r.w) : "l"(acc[i][1]));
        *(float4*)(ob + (size_t)i*H_) = r;
    }
}

// ---------------- launch ----------------
extern "C" void kernel_launch(void* const* d_in, const int* in_sizes, int n_in,
                              void* d_out, int out_size) {
    const float* z     = (const float*)d_in[0];
    const void*  ls    = d_in[1];
    const float* zmask = (const float*)d_in[2];
    const float* sigma = (const float*)d_in[3];
    float* out  = (float*)d_out;
    float* outm = out + (size_t)B_*LOUT_*H_;

    kn_kernel<<<B_, 256>>>(zmask);
    k1c_kernel<<<dim3(NCH, B_), 256>>>(z);
    k1p_kernel<<<dim3(4, B_), 256>>>();
    kw_kernel<<<NTILES_TOT, 64>>>(ls, sigma, outm);
    k2_kernel<<<dim3(2, NTILE, B_), 256>>>(z, out);
}